// round 3
// baseline (speedup 1.0000x reference)
#include <cuda_runtime.h>

#define BATCH 2
#define NVERT 20000
#define NRINGS 8
#define NDIRS 8
#define CH 16
#define NF 16
#define VPB 16           // vertices per block
#define THREADS 256

typedef unsigned long long ull;

// smem layout (floats)
#define SK_FLOATS (NRINGS*NDIRS*CH*NF)        // 16384
#define ZD_STRIDE 132                          // padded d-stride (floats)
#define ZV_STRIDE (NDIRS*ZD_STRIDE)            // 1056 per (b,v)
#define SZ_FLOATS (BATCH*VPB*ZV_STRIDE)        // 33792
#define SCK_FLOATS (CH*NF)                     // 256
#define SB_FLOATS  (NF)                        // 16
#define SMEM_FLOATS (SK_FLOATS + SZ_FLOATS + SCK_FLOATS + SB_FLOATS)
#define SMEM_BYTES  (SMEM_FLOATS * 4)

__device__ __forceinline__ ull pack2(float a, float b) {
    ull r; asm("mov.b64 %0, {%1, %2};" : "=l"(r) : "f"(a), "f"(b)); return r;
}
__device__ __forceinline__ float2 unpack2(ull v) {
    float2 r; asm("mov.b64 {%0, %1}, %2;" : "=f"(r.x), "=f"(r.y) : "l"(v)); return r;
}
__device__ __forceinline__ void fma2(ull& d, ull a, ull b) {
    asm("fma.rn.f32x2 %0, %1, %2, %0;" : "+l"(d) : "l"(a), "l"(b));
}

__global__ __launch_bounds__(THREADS, 1)
void geodesic_conv_kernel(const float* __restrict__ y,
                          const int*   __restrict__ contributors,
                          const float* __restrict__ weights_bary,
                          const int*   __restrict__ angles,
                          const float* __restrict__ kern,
                          const float* __restrict__ center_kernel,
                          const float* __restrict__ bias,
                          float*       __restrict__ out)
{
    extern __shared__ float smem[];
    float* sK  = smem;                 // [ (r*8+dw)*16 + c ][ f ] == input layout
    float* sZ  = sK + SK_FLOATS;       // [b][v][d][r][c] with padded strides
    float* sCK = sZ + SZ_FLOATS;       // [c][f]
    float* sB  = sCK + SCK_FLOATS;     // [f]

    const int tid = threadIdx.x;
    const int v0  = blockIdx.x * VPB;

    // ---- load conv kernel / center kernel / bias into smem ----
    {
        const float4* K4 = (const float4*)kern;
        float4* sK4 = (float4*)sK;
        #pragma unroll
        for (int i = 0; i < SK_FLOATS/4/THREADS; ++i)
            sK4[tid + i*THREADS] = K4[tid + i*THREADS];
        if (tid < SCK_FLOATS/4)
            ((float4*)sCK)[tid] = ((const float4*)center_kernel)[tid];
        if (tid < SB_FLOATS)
            sB[tid] = bias[tid];
    }

    // ---- gather phase: build z[b,v,d,r,c] in smem ----
    // one thread per (b,v,r,d) row: 2048 tasks, 8 per thread.
    // index loads read once (not 4x); each task has 12 independent y LDG.128.
    const float4* y4 = (const float4*)y;
    {
        #pragma unroll 1
        for (int i = 0; i < (BATCH*VPB*NRINGS*NDIRS)/THREADS; ++i) {
            int g = tid + i*THREADS;              // 0..2047
            int d = g & 7;
            int r = (g >> 3) & 7;
            int b = (g >> 6) & 1;
            int v = (g >> 7) & (VPB-1);
            int ibase = (((v0 + v)*NRINGS + r)*NDIRS + d)*3;

            int   i0 = contributors[ibase+0]*NDIRS + angles[ibase+0];
            int   i1 = contributors[ibase+1]*NDIRS + angles[ibase+1];
            int   i2 = contributors[ibase+2]*NDIRS + angles[ibase+2];
            float w0 = weights_bary[ibase+0];
            float w1 = weights_bary[ibase+1];
            float w2 = weights_bary[ibase+2];

            const float4* p0 = &y4[(b*NVERT*NDIRS + i0)*4];
            const float4* p1 = &y4[(b*NVERT*NDIRS + i1)*4];
            const float4* p2 = &y4[(b*NVERT*NDIRS + i2)*4];
            float4 a0[4], a1[4], a2[4];
            #pragma unroll
            for (int q = 0; q < 4; ++q) a0[q] = __ldg(&p0[q]);
            #pragma unroll
            for (int q = 0; q < 4; ++q) a1[q] = __ldg(&p1[q]);
            #pragma unroll
            for (int q = 0; q < 4; ++q) a2[q] = __ldg(&p2[q]);

            float* zrow = &sZ[(b*VPB + v)*ZV_STRIDE + d*ZD_STRIDE + r*16];
            #pragma unroll
            for (int q = 0; q < 4; ++q) {
                float4 acc;
                acc.x = w0*a0[q].x + w1*a1[q].x + w2*a2[q].x;
                acc.y = w0*a0[q].y + w1*a1[q].y + w2*a2[q].y;
                acc.z = w0*a0[q].z + w1*a1[q].z + w2*a2[q].z;
                acc.w = w0*a0[q].w + w1*a1[q].w + w2*a2[q].w;
                *(float4*)&zrow[q*4] = acc;
            }
        }
    }
    __syncthreads();

    // ---- conv phase ----
    // thread -> (v, d) row + f-half; computes both batches, 8+8 floats as f32x2
    const int rowid = tid >> 1;
    const int v  = rowid >> 3;
    const int d  = rowid & 7;
    const int fh = tid & 1;
    const int fbase = fh * 8;
    const int gv = v0 + v;

    ull acc0[4], acc1[4];
    #pragma unroll
    for (int j = 0; j < 4; ++j) { acc0[j] = 0ull; acc1[j] = 0ull; }

    const float* z0base = sZ + v*ZV_STRIDE;
    const float* z1base = sZ + (VPB + v)*ZV_STRIDE;

    #pragma unroll 1
    for (int dw = 0; dw < 8; ++dw) {
        int dp = (d + dw) & 7;
        const float* z0 = z0base + dp*ZD_STRIDE;
        const float* z1 = z1base + dp*ZD_STRIDE;
        const float* kp = sK + dw*(CH*NF) + fbase;    // K row (r=0,c=0) for this dw
        #pragma unroll 1
        for (int r = 0; r < 8; ++r) {
            // ---- batch ALL loads for this (dw,r) into registers first ----
            float zv0[16], zv1[16];
            #pragma unroll
            for (int q = 0; q < 4; ++q) {
                *(float4*)&zv0[q*4] = *(const float4*)(z0 + r*16 + q*4);
                *(float4*)&zv1[q*4] = *(const float4*)(z1 + r*16 + q*4);
            }
            const float* kr = kp + r*(NDIRS*CH*NF);   // + r*2048
            ull kk[64];                                // 16 c x (kA.x,kA.y,kB.x,kB.y)
            #pragma unroll
            for (int c = 0; c < 16; ++c) {
                ulonglong2 kA = *(const ulonglong2*)(kr + c*NF);
                ulonglong2 kB = *(const ulonglong2*)(kr + c*NF + 4);
                kk[c*4+0] = kA.x; kk[c*4+1] = kA.y;
                kk[c*4+2] = kB.x; kk[c*4+3] = kB.y;
            }
            // ---- then the FFMA2 burst ----
            #pragma unroll
            for (int c = 0; c < 16; ++c) {
                ull aa = pack2(zv0[c], zv0[c]);
                ull bb = pack2(zv1[c], zv1[c]);
                fma2(acc0[0], aa, kk[c*4+0]); fma2(acc0[1], aa, kk[c*4+1]);
                fma2(acc0[2], aa, kk[c*4+2]); fma2(acc0[3], aa, kk[c*4+3]);
                fma2(acc1[0], bb, kk[c*4+0]); fma2(acc1[1], bb, kk[c*4+1]);
                fma2(acc1[2], bb, kk[c*4+2]); fma2(acc1[3], bb, kk[c*4+3]);
            }
        }
    }

    // ---- center term: out += y[b,v,d,:] @ center_kernel ----
    {
        float cy0[16], cy1[16];
        const float4* yr0 = (const float4*)(y + ((0*NVERT + gv)*NDIRS + d)*CH);
        const float4* yr1 = (const float4*)(y + ((1*NVERT + gv)*NDIRS + d)*CH);
        #pragma unroll
        for (int q = 0; q < 4; ++q) {
            *(float4*)&cy0[q*4] = __ldg(&yr0[q]);
            *(float4*)&cy1[q*4] = __ldg(&yr1[q]);
        }
        #pragma unroll
        for (int c = 0; c < 16; ++c) {
            ulonglong2 kA = *(const ulonglong2*)&sCK[c*NF + fbase];
            ulonglong2 kB = *(const ulonglong2*)&sCK[c*NF + fbase + 4];
            ull aa = pack2(cy0[c], cy0[c]);
            ull bb = pack2(cy1[c], cy1[c]);
            fma2(acc0[0], aa, kA.x); fma2(acc0[1], aa, kA.y);
            fma2(acc0[2], aa, kB.x); fma2(acc0[3], aa, kB.y);
            fma2(acc1[0], bb, kA.x); fma2(acc1[1], bb, kA.y);
            fma2(acc1[2], bb, kB.x); fma2(acc1[3], bb, kB.y);
        }
    }

    // ---- bias, max over d (lane bits 1..3), relu, write ----
    float r0[8], r1[8];
    #pragma unroll
    for (int j = 0; j < 4; ++j) {
        float2 x0 = unpack2(acc0[j]);
        float2 x1 = unpack2(acc1[j]);
        r0[j*2+0] = x0.x; r0[j*2+1] = x0.y;
        r1[j*2+0] = x1.x; r1[j*2+1] = x1.y;
    }
    #pragma unroll
    for (int j = 0; j < 8; ++j) {
        float x0 = r0[j] + sB[fbase + j];
        float x1 = r1[j] + sB[fbase + j];
        #pragma unroll
        for (int m = 2; m <= 8; m <<= 1) {
            x0 = fmaxf(x0, __shfl_xor_sync(0xffffffffu, x0, m));
            x1 = fmaxf(x1, __shfl_xor_sync(0xffffffffu, x1, m));
        }
        r0[j] = fmaxf(x0, 0.f);
        r1[j] = fmaxf(x1, 0.f);
    }

    if (d == 0) {
        float4* o4 = (float4*)out;
        o4[(0*NVERT + gv)*4 + fh*2 + 0] = *(float4*)&r0[0];
        o4[(0*NVERT + gv)*4 + fh*2 + 1] = *(float4*)&r0[4];
        o4[(1*NVERT + gv)*4 + fh*2 + 0] = *(float4*)&r1[0];
        o4[(1*NVERT + gv)*4 + fh*2 + 1] = *(float4*)&r1[4];
    }
}

extern "C" void kernel_launch(void* const* d_in, const int* in_sizes, int n_in,
                              void* d_out, int out_size)
{
    (void)in_sizes; (void)n_in; (void)out_size;
    const float* y            = (const float*)d_in[0];
    const int*   contributors = (const int*)  d_in[1];
    const float* weights_bary = (const float*)d_in[2];
    const int*   angles       = (const int*)  d_in[3];
    const float* kern         = (const float*)d_in[4];
    const float* center_k     = (const float*)d_in[5];
    const float* bias         = (const float*)d_in[6];
    float* out = (float*)d_out;

    cudaFuncSetAttribute(geodesic_conv_kernel,
                         cudaFuncAttributeMaxDynamicSharedMemorySize, SMEM_BYTES);

    dim3 grid(NVERT / VPB);   // 1250
    dim3 block(THREADS);
    geodesic_conv_kernel<<<grid, block, SMEM_BYTES>>>(
        y, contributors, weights_bary, angles, kern, center_k, bias, out);
}

// round 5
// speedup vs baseline: 1.2421x; 1.2421x over previous
#include <cuda_runtime.h>
#include <cuda_bf16.h>
#include <cstdint>

typedef uint32_t u32; typedef uint64_t u64;

#define NVERT 20000
#define NDIRS 8
#define THREADS 256
#define NTILES 313            // ceil(40000/128) row tiles of 128
#define NCHUNKS 9             // 8 rings + 1 center chunk, Kc=128 each

// ---- B chunk images (hi/lo bf16), pre-swizzled, rebuilt each launch ----
__device__ __nv_bfloat16 gBh[NCHUNKS][16384];   // [chunk][128n x 128k tile image]
__device__ __nv_bfloat16 gBl[NCHUNKS][16384];

// tile byte offset for element (row, k) in a 128x128 bf16 tile:
// row stride 256B; 16B chunks XOR-swizzled by (row&7) for conflict-free LDSM
__device__ __host__ __forceinline__ u32 tile_off(int row, int k) {
    return (u32)(row * 256 + (((k >> 3) ^ (row & 7)) << 4) + (k & 7) * 2);
}

__device__ __forceinline__ u32 smem_u32(const void* p) {
    u32 a; asm("{ .reg .u64 t; cvta.to.shared.u64 t, %1; cvt.u32.u64 %0, t; }" : "=r"(a) : "l"(p));
    return a;
}
__device__ __forceinline__ void ldsm4(u32 r[4], u32 addr) {
    asm volatile("ldmatrix.sync.aligned.m8n8.x4.shared.b16 {%0,%1,%2,%3}, [%4];"
                 : "=r"(r[0]), "=r"(r[1]), "=r"(r[2]), "=r"(r[3]) : "r"(addr));
}
__device__ __forceinline__ void mma16816(float c[4], const u32 a[4], u32 b0, u32 b1) {
    asm volatile(
        "mma.sync.aligned.m16n8k16.row.col.f32.bf16.bf16.f32 "
        "{%0,%1,%2,%3}, {%4,%5,%6,%7}, {%8,%9}, {%0,%1,%2,%3};"
        : "+f"(c[0]), "+f"(c[1]), "+f"(c[2]), "+f"(c[3])
        : "r"(a[0]), "r"(a[1]), "r"(a[2]), "r"(a[3]), "r"(b0), "r"(b1));
}

// ---- prep kernel: build swizzled bf16 hi/lo B-chunk images ----
// N index: n = f*8 + d.  K index within chunk: k = dp*16 + c.
__global__ void prep_B(const float* __restrict__ kern, const float* __restrict__ ck) {
    int id = blockIdx.x * blockDim.x + threadIdx.x;     // 9*128*128 = 147456
    if (id >= NCHUNKS * 128 * 128) return;
    int k  = id & 127;
    int n  = (id >> 7) & 127;
    int kc = id >> 14;
    int f = n >> 3, d = n & 7;
    int dp = k >> 4, c = k & 15;
    float val;
    if (kc < 8) {
        int dw = (dp - d) & 7;
        val = kern[((kc * 8 + dw) * 16 + c) * 16 + f];
    } else {
        val = (dp == d) ? ck[c * 16 + f] : 0.f;
    }
    __nv_bfloat16 hi = __float2bfloat16(val);
    __nv_bfloat16 lo = __float2bfloat16(val - __bfloat162float(hi));
    u32 e = tile_off(n, k) >> 1;
    gBh[kc][e] = hi;
    gBl[kc][e] = lo;
}

// ---- smem layout (byte offsets) ----
#define SAH 0
#define SAL 32768
#define SBH 65536
#define SBL 98304
#define SMEM_TOTAL 131072

// split one 16-float row segment (k = dp*16 .. +15) into hi/lo bf16 images
__device__ __forceinline__ void store_row(char* sm, int m, int dp, const float* z) {
    #pragma unroll
    for (int g = 0; g < 2; ++g) {
        u32 H[4], L[4];
        #pragma unroll
        for (int q = 0; q < 4; ++q) {
            float a = z[g*8 + 2*q], b = z[g*8 + 2*q + 1];
            __nv_bfloat16 ha = __float2bfloat16(a);
            __nv_bfloat16 hb = __float2bfloat16(b);
            __nv_bfloat162 hh; hh.x = ha; hh.y = hb;
            __nv_bfloat162 ll;
            ll.x = __float2bfloat16(a - __bfloat162float(ha));
            ll.y = __float2bfloat16(b - __bfloat162float(hb));
            H[q] = *reinterpret_cast<u32*>(&hh);
            L[q] = *reinterpret_cast<u32*>(&ll);
        }
        u32 off = (u32)(m * 256 + (((dp*2 + g) ^ (m & 7)) << 4));
        *reinterpret_cast<uint4*>(sm + SAH + off) = make_uint4(H[0],H[1],H[2],H[3]);
        *reinterpret_cast<uint4*>(sm + SAL + off) = make_uint4(L[0],L[1],L[2],L[3]);
    }
}

__global__ __launch_bounds__(THREADS, 1)
void geodesic_hmma_kernel(const float* __restrict__ y,
                          const int*   __restrict__ contributors,
                          const float* __restrict__ weights_bary,
                          const int*   __restrict__ angles,
                          const float* __restrict__ bias,
                          float*       __restrict__ out)
{
    extern __shared__ char sm[];
    const u32 smb = smem_u32(sm);
    const int tid = threadIdx.x;
    const int wid = tid >> 5;
    const int lid = tid & 31;
    const int v0  = blockIdx.x * 64;            // 64 vertices => 128 rows (m = vl*2 + b)
    const int m0  = wid * 16;                   // warp's m-strip

    // accumulators: 16 n-tiles x 4 fp32
    float acc[64];
    #pragma unroll
    for (int i = 0; i < 64; ++i) acc[i] = 0.f;

    // per-lane ldmatrix row geometry (shared by A and B addressing)
    const int lrow = (lid & 7) + ((lid >> 3) & 1) * 8;   // row within 16-row tile pair
    const int khalf = (lid >> 4);                        // 0/1 -> +8 in k

    const float4* y4 = (const float4*)y;

    #pragma unroll 1
    for (int kc = 0; kc < NCHUNKS; ++kc) {
        if (kc > 0) __syncthreads();    // all warps done with previous chunk's smem

        // ---- build A chunk (gather rings; chunk 8 = raw y) ----
        #pragma unroll 1
        for (int it = 0; it < 2; ++it) {
            int t  = tid + it * THREADS;            // 0..511
            int dp = t & 7;
            int vl = t >> 3;                         // 0..63
            int v  = v0 + vl;
            float z0[16], z1[16];
            if (v < NVERT) {
                if (kc < 8) {
                    int ibase = ((v * 8 + kc) * 8 + dp) * 3;
                    int   i0 = contributors[ibase+0] * 8 + angles[ibase+0];
                    int   i1 = contributors[ibase+1] * 8 + angles[ibase+1];
                    int   i2 = contributors[ibase+2] * 8 + angles[ibase+2];
                    float w0 = weights_bary[ibase+0];
                    float w1 = weights_bary[ibase+1];
                    float w2 = weights_bary[ibase+2];
                    const float4* p00 = y4 + (u32)i0 * 4;
                    const float4* p01 = y4 + (u32)i1 * 4;
                    const float4* p02 = y4 + (u32)i2 * 4;
                    const float4* p10 = p00 + NVERT * NDIRS * 4;
                    const float4* p11 = p01 + NVERT * NDIRS * 4;
                    const float4* p12 = p02 + NVERT * NDIRS * 4;
                    float4 a0[4], a1[4], a2[4], b0[4], b1[4], b2[4];
                    #pragma unroll
                    for (int q = 0; q < 4; ++q) { a0[q]=__ldg(p00+q); a1[q]=__ldg(p01+q); a2[q]=__ldg(p02+q);
                                                  b0[q]=__ldg(p10+q); b1[q]=__ldg(p11+q); b2[q]=__ldg(p12+q); }
                    #pragma unroll
                    for (int q = 0; q < 4; ++q) {
                        z0[q*4+0] = w0*a0[q].x + w1*a1[q].x + w2*a2[q].x;
                        z0[q*4+1] = w0*a0[q].y + w1*a1[q].y + w2*a2[q].y;
                        z0[q*4+2] = w0*a0[q].z + w1*a1[q].z + w2*a2[q].z;
                        z0[q*4+3] = w0*a0[q].w + w1*a1[q].w + w2*a2[q].w;
                        z1[q*4+0] = w0*b0[q].x + w1*b1[q].x + w2*b2[q].x;
                        z1[q*4+1] = w0*b0[q].y + w1*b1[q].y + w2*b2[q].y;
                        z1[q*4+2] = w0*b0[q].z + w1*b1[q].z + w2*b2[q].z;
                        z1[q*4+3] = w0*b0[q].w + w1*b1[q].w + w2*b2[q].w;
                    }
                } else {
                    int idx = v * 8 + dp;
                    const float4* p0 = y4 + (u32)idx * 4;
                    const float4* p1 = p0 + NVERT * NDIRS * 4;
                    #pragma unroll
                    for (int q = 0; q < 4; ++q) {
                        float4 a = __ldg(p0+q), b = __ldg(p1+q);
                        z0[q*4+0]=a.x; z0[q*4+1]=a.y; z0[q*4+2]=a.z; z0[q*4+3]=a.w;
                        z1[q*4+0]=b.x; z1[q*4+1]=b.y; z1[q*4+2]=b.z; z1[q*4+3]=b.w;
                    }
                }
            } else {
                #pragma unroll
                for (int q = 0; q < 16; ++q) { z0[q] = 0.f; z1[q] = 0.f; }
            }
            store_row(sm, vl*2 + 0, dp, z0);
            store_row(sm, vl*2 + 1, dp, z1);
        }

        // ---- copy B chunk images (L2-resident global -> smem) ----
        {
            const uint4* sh = (const uint4*)(&gBh[kc][0]);
            const uint4* sl = (const uint4*)(&gBl[kc][0]);
            uint4* dh = (uint4*)(sm + SBH);
            uint4* dl = (uint4*)(sm + SBL);
            #pragma unroll
            for (int i = 0; i < 2048 / THREADS; ++i) {
                dh[tid + i*THREADS] = __ldg(sh + tid + i*THREADS);
                dl[tid + i*THREADS] = __ldg(sl + tid + i*THREADS);
            }
        }

        __syncthreads();

        // ---- HMMA: 3 splits x 8 ksteps x (1 A-ldsm + 8 B-ldsm + 16 mma) ----
        const u32 abase[3] = { smb + SAH, smb + SAH, smb + SAL };
        const u32 bbase[3] = { smb + SBH, smb + SBL, smb + SBH };
        const int mA = m0 + lrow;
        #pragma unroll 1
        for (int s = 0; s < 3; ++s) {
            u32 sa = abase[s], sb = bbase[s];
            #pragma unroll 1
            for (int ks = 0; ks < 8; ++ks) {
                int cchunk = ks*2 + khalf;                // 16B-chunk column index
                u32 a_addr = sa + (u32)(mA*256 + ((cchunk ^ (mA & 7)) << 4));
                u32 af[4];
                ldsm4(af, a_addr);
                #pragma unroll
                for (int p = 0; p < 8; ++p) {
                    int nB = p*16 + lrow;
                    u32 b_addr = sb + (u32)(nB*256 + ((cchunk ^ (nB & 7)) << 4));
                    u32 bf[4];
                    ldsm4(bf, b_addr);
                    mma16816(&acc[(p*2+0)*4], af, bf[0], bf[2]);
                    mma16816(&acc[(p*2+1)*4], af, bf[1], bf[3]);
                }
            }
        }
    }

    // ---- epilogue: bias + relu + max over d, write out ----
    // c-frag: acc[nt*4+{0,1}] = C[m0+lid/4][n=nt*8+(lid%4)*2+{0,1}]
    //         acc[nt*4+{2,3}] = same cols, row +8.   n = f*8 + d  ->  f=nt, d=(lid%4)*2+{0,1}
    #pragma unroll
    for (int nt = 0; nt < 16; ++nt) {
        float mlo = fmaxf(acc[nt*4+0], acc[nt*4+1]);
        float mhi = fmaxf(acc[nt*4+2], acc[nt*4+3]);
        mlo = fmaxf(mlo, __shfl_xor_sync(0xffffffffu, mlo, 1));
        mlo = fmaxf(mlo, __shfl_xor_sync(0xffffffffu, mlo, 2));
        mhi = fmaxf(mhi, __shfl_xor_sync(0xffffffffu, mhi, 1));
        mhi = fmaxf(mhi, __shfl_xor_sync(0xffffffffu, mhi, 2));
        if ((lid & 3) == (nt & 3)) {
            float bf_ = __ldg(&bias[nt]);
            int r = m0 + (lid >> 2);
            int b = r & 1, v = v0 + (r >> 1);
            if (v < NVERT) out[((u32)b * NVERT + v) * 16 + nt] = fmaxf(mlo + bf_, 0.f);
            r += 8; b = r & 1; v = v0 + (r >> 1);
            if (v < NVERT) out[((u32)b * NVERT + v) * 16 + nt] = fmaxf(mhi + bf_, 0.f);
        }
    }
}

extern "C" void kernel_launch(void* const* d_in, const int* in_sizes, int n_in,
                              void* d_out, int out_size)
{
    (void)in_sizes; (void)n_in; (void)out_size;
    const float* y            = (const float*)d_in[0];
    const int*   contributors = (const int*)  d_in[1];
    const float* weights_bary = (const float*)d_in[2];
    const int*   angles       = (const int*)  d_in[3];
    const float* kern         = (const float*)d_in[4];
    const float* center_k     = (const float*)d_in[5];
    const float* bias         = (const float*)d_in[6];
    float* out = (float*)d_out;

    prep_B<<<(NCHUNKS*128*128 + 255)/256, 256>>>(kern, center_k);

    cudaFuncSetAttribute(geodesic_hmma_kernel,
                         cudaFuncAttributeMaxDynamicSharedMemorySize, SMEM_TOTAL);
    geodesic_hmma_kernel<<<NTILES, THREADS, SMEM_TOTAL>>>(
        y, contributors, weights_bary, angles, bias, out);
}

// round 6
// speedup vs baseline: 1.5233x; 1.2263x over previous
#include <cuda_runtime.h>
#include <cuda_bf16.h>
#include <cstdint>

typedef uint32_t u32; typedef uint64_t u64;

#define NVERT 20000
#define NDIRS 8
#define THREADS 256
#define VTILE 32              // vertices per CTA  -> 64 m-rows
#define NTILES 625            // 20000/32 exact
#define NCHUNKS 9             // 8 rings + 1 center chunk, Kc=128 each

// ---- B chunk images (hi/lo bf16), pre-swizzled, rebuilt each launch ----
__device__ __align__(16) __nv_bfloat16 gBh[NCHUNKS][16384];   // [chunk][128n x 128k]
__device__ __align__(16) __nv_bfloat16 gBl[NCHUNKS][16384];

// element (row,k) byte offset in a row-major tile: row stride 256B,
// 16B chunks XOR-swizzled by (row&7) -> conflict-free LDSM
__device__ __host__ __forceinline__ u32 tile_off(int row, int k) {
    return (u32)(row * 256 + (((k >> 3) ^ (row & 7)) << 4) + (k & 7) * 2);
}

__device__ __forceinline__ u32 smem_u32(const void* p) {
    u32 a; asm("{ .reg .u64 t; cvta.to.shared.u64 t, %1; cvt.u32.u64 %0, t; }" : "=r"(a) : "l"(p));
    return a;
}
__device__ __forceinline__ void ldsm4(u32 r[4], u32 addr) {
    asm volatile("ldmatrix.sync.aligned.m8n8.x4.shared.b16 {%0,%1,%2,%3}, [%4];"
                 : "=r"(r[0]), "=r"(r[1]), "=r"(r[2]), "=r"(r[3]) : "r"(addr));
}
__device__ __forceinline__ void mma16816(float c[4], const u32 a[4], u32 b0, u32 b1) {
    asm volatile(
        "mma.sync.aligned.m16n8k16.row.col.f32.bf16.bf16.f32 "
        "{%0,%1,%2,%3}, {%4,%5,%6,%7}, {%8,%9}, {%0,%1,%2,%3};"
        : "+f"(c[0]), "+f"(c[1]), "+f"(c[2]), "+f"(c[3])
        : "r"(a[0]), "r"(a[1]), "r"(a[2]), "r"(a[3]), "r"(b0), "r"(b1));
}
__device__ __forceinline__ void cp16(u32 dst, const void* src) {
    asm volatile("cp.async.cg.shared.global [%0], [%1], 16;" :: "r"(dst), "l"(src) : "memory");
}
__device__ __forceinline__ void cp_commit_waitall() {
    asm volatile("cp.async.commit_group;\n\tcp.async.wait_group 0;" ::: "memory");
}

// ---- prep kernel: build swizzled bf16 hi/lo B-chunk images ----
// n = f*8 + d ; k = dp*16 + c
__global__ void prep_B(const float* __restrict__ kern, const float* __restrict__ ck) {
    int id = blockIdx.x * blockDim.x + threadIdx.x;     // 147456
    if (id >= NCHUNKS * 128 * 128) return;
    int k  = id & 127;
    int n  = (id >> 7) & 127;
    int kc = id >> 14;
    int f = n >> 3, d = n & 7;
    int dp = k >> 4, c = k & 15;
    float val;
    if (kc < 8) {
        int dw = (dp - d) & 7;
        val = kern[((kc * 8 + dw) * 16 + c) * 16 + f];
    } else {
        val = (dp == d) ? ck[c * 16 + f] : 0.f;
    }
    __nv_bfloat16 hi = __float2bfloat16(val);
    __nv_bfloat16 lo = __float2bfloat16(val - __bfloat162float(hi));
    u32 e = tile_off(n, k) >> 1;
    gBh[kc][e] = hi;
    gBl[kc][e] = lo;
}

// ---- smem layout (byte offsets): A 64x128 hi/lo + B 128x128 hi/lo = 96 KB ----
#define SAH 0
#define SAL 16384
#define SBH 32768
#define SBL 65536
#define SMEM_TOTAL 98304

// split one 16-float k-segment into hi/lo bf16 and store into both A images
__device__ __forceinline__ void store_row(char* sm, int m, int dp, const float* z) {
    #pragma unroll
    for (int g = 0; g < 2; ++g) {
        u32 H[4], L[4];
        #pragma unroll
        for (int q = 0; q < 4; ++q) {
            float a = z[g*8 + 2*q], b = z[g*8 + 2*q + 1];
            __nv_bfloat16 ha = __float2bfloat16(a);
            __nv_bfloat16 hb = __float2bfloat16(b);
            __nv_bfloat162 hh; hh.x = ha; hh.y = hb;
            __nv_bfloat162 ll;
            ll.x = __float2bfloat16(a - __bfloat162float(ha));
            ll.y = __float2bfloat16(b - __bfloat162float(hb));
            H[q] = *reinterpret_cast<u32*>(&hh);
            L[q] = *reinterpret_cast<u32*>(&ll);
        }
        u32 off = (u32)(m * 256 + (((dp*2 + g) ^ (m & 7)) << 4));
        *reinterpret_cast<uint4*>(sm + SAH + off) = make_uint4(H[0],H[1],H[2],H[3]);
        *reinterpret_cast<uint4*>(sm + SAL + off) = make_uint4(L[0],L[1],L[2],L[3]);
    }
}

__global__ __launch_bounds__(THREADS, 2)
void geodesic_hmma_kernel(const float* __restrict__ y,
                          const int*   __restrict__ contributors,
                          const float* __restrict__ weights_bary,
                          const int*   __restrict__ angles,
                          const float* __restrict__ bias,
                          float*       __restrict__ out)
{
    extern __shared__ char sm[];
    const u32 smb = smem_u32(sm);
    const int tid = threadIdx.x;
    const int wid = tid >> 5;
    const int lid = tid & 31;
    const int v0  = blockIdx.x * VTILE;         // 32 vertices => 64 rows (m = vl*2 + b)
    const int m0  = (wid >> 1) * 16;            // warp's 16-row m-strip (4 strips)
    const int nh  = wid & 1;                    // warp's n-half (64 cols)

    // accumulators: 8 n-tiles x 4 fp32
    float acc[32];
    #pragma unroll
    for (int i = 0; i < 32; ++i) acc[i] = 0.f;

    const int lrow  = (lid & 7) + ((lid >> 3) & 1) * 8;
    const int khalf = (lid >> 4);

    const float4* y4 = (const float4*)y;

    #pragma unroll 1
    for (int kc = 0; kc < NCHUNKS; ++kc) {
        if (kc > 0) __syncthreads();       // everyone done reading A and B of prev chunk

        // ---- issue async B-chunk copy first (hides under gather) ----
        {
            const char* sh = (const char*)(&gBh[kc][0]);
            const char* sl = (const char*)(&gBl[kc][0]);
            #pragma unroll
            for (int i = 0; i < 8; ++i) {
                u32 off = (u32)(tid + i * THREADS) * 16;
                cp16(smb + SBH + off, sh + off);
                cp16(smb + SBL + off, sl + off);
            }
        }

        // ---- gather: one (v,dp) task per thread ----
        {
            int dp = tid & 7;
            int vl = tid >> 3;                   // 0..31
            int v  = v0 + vl;
            float z0[16], z1[16];
            if (kc < 8) {
                int ibase = ((v * 8 + kc) * 8 + dp) * 3;
                int   i0 = contributors[ibase+0] * 8 + angles[ibase+0];
                int   i1 = contributors[ibase+1] * 8 + angles[ibase+1];
                int   i2 = contributors[ibase+2] * 8 + angles[ibase+2];
                float w0 = weights_bary[ibase+0];
                float w1 = weights_bary[ibase+1];
                float w2 = weights_bary[ibase+2];
                const float4* p00 = y4 + (u32)i0 * 4;
                const float4* p01 = y4 + (u32)i1 * 4;
                const float4* p02 = y4 + (u32)i2 * 4;
                const float4* p10 = p00 + NVERT * NDIRS * 4;
                const float4* p11 = p01 + NVERT * NDIRS * 4;
                const float4* p12 = p02 + NVERT * NDIRS * 4;
                float4 a0[4], a1[4], a2[4], b0[4], b1[4], b2[4];
                #pragma unroll
                for (int q = 0; q < 4; ++q) { a0[q]=__ldg(p00+q); a1[q]=__ldg(p01+q); a2[q]=__ldg(p02+q);
                                              b0[q]=__ldg(p10+q); b1[q]=__ldg(p11+q); b2[q]=__ldg(p12+q); }
                #pragma unroll
                for (int q = 0; q < 4; ++q) {
                    z0[q*4+0] = w0*a0[q].x + w1*a1[q].x + w2*a2[q].x;
                    z0[q*4+1] = w0*a0[q].y + w1*a1[q].y + w2*a2[q].y;
                    z0[q*4+2] = w0*a0[q].z + w1*a1[q].z + w2*a2[q].z;
                    z0[q*4+3] = w0*a0[q].w + w1*a1[q].w + w2*a2[q].w;
                    z1[q*4+0] = w0*b0[q].x + w1*b1[q].x + w2*b2[q].x;
                    z1[q*4+1] = w0*b0[q].y + w1*b1[q].y + w2*b2[q].y;
                    z1[q*4+2] = w0*b0[q].z + w1*b1[q].z + w2*b2[q].z;
                    z1[q*4+3] = w0*b0[q].w + w1*b1[q].w + w2*b2[q].w;
                }
            } else {
                int idx = v * 8 + dp;
                const float4* p0 = y4 + (u32)idx * 4;
                const float4* p1 = p0 + NVERT * NDIRS * 4;
                #pragma unroll
                for (int q = 0; q < 4; ++q) {
                    float4 a = __ldg(p0+q), b = __ldg(p1+q);
                    z0[q*4+0]=a.x; z0[q*4+1]=a.y; z0[q*4+2]=a.z; z0[q*4+3]=a.w;
                    z1[q*4+0]=b.x; z1[q*4+1]=b.y; z1[q*4+2]=b.z; z1[q*4+3]=b.w;
                }
            }
            store_row(sm, vl*2 + 0, dp, z0);
            store_row(sm, vl*2 + 1, dp, z1);
        }

        cp_commit_waitall();
        __syncthreads();

        // ---- HMMA: 3 splits x 8 ksteps; this warp: 1 m-strip x 64 n-cols ----
        const u32 abase[3] = { smb + SAH, smb + SAH, smb + SAL };
        const u32 bbase[3] = { smb + SBH, smb + SBL, smb + SBH };
        const int mA = m0 + lrow;
        #pragma unroll 1
        for (int s = 0; s < 3; ++s) {
            u32 sa = abase[s], sb = bbase[s];
            #pragma unroll 1
            for (int ks = 0; ks < 8; ++ks) {
                int cchunk = ks*2 + khalf;
                u32 af[4];
                ldsm4(af, sa + (u32)(mA*256 + ((cchunk ^ (mA & 7)) << 4)));
                #pragma unroll
                for (int p = 0; p < 4; ++p) {
                    int nB = nh*64 + p*16 + lrow;
                    u32 bf[4];
                    ldsm4(bf, sb + (u32)(nB*256 + ((cchunk ^ (nB & 7)) << 4)));
                    mma16816(&acc[(p*2+0)*4], af, bf[0], bf[2]);
                    mma16816(&acc[(p*2+1)*4], af, bf[1], bf[3]);
                }
            }
        }
    }

    // ---- epilogue: bias + relu + max over d ----
    // ntile (global) = nh*8 + p*2 + j = f ;  d = (lid&3)*2 + {0,1}
    #pragma unroll
    for (int t = 0; t < 8; ++t) {
        int f = nh*8 + t;
        float mlo = fmaxf(acc[t*4+0], acc[t*4+1]);
        float mhi = fmaxf(acc[t*4+2], acc[t*4+3]);
        mlo = fmaxf(mlo, __shfl_xor_sync(0xffffffffu, mlo, 1));
        mlo = fmaxf(mlo, __shfl_xor_sync(0xffffffffu, mlo, 2));
        mhi = fmaxf(mhi, __shfl_xor_sync(0xffffffffu, mhi, 1));
        mhi = fmaxf(mhi, __shfl_xor_sync(0xffffffffu, mhi, 2));
        if ((lid & 3) == (t & 3)) {
            float bf_ = __ldg(&bias[f]);
            int r = m0 + (lid >> 2);
            int b = r & 1, v = v0 + (r >> 1);
            out[((u32)b * NVERT + v) * 16 + f] = fmaxf(mlo + bf_, 0.f);
            r += 8; b = r & 1; v = v0 + (r >> 1);
            out[((u32)b * NVERT + v) * 16 + f] = fmaxf(mhi + bf_, 0.f);
        }
    }
}

extern "C" void kernel_launch(void* const* d_in, const int* in_sizes, int n_in,
                              void* d_out, int out_size)
{
    (void)in_sizes; (void)n_in; (void)out_size;
    const float* y            = (const float*)d_in[0];
    const int*   contributors = (const int*)  d_in[1];
    const float* weights_bary = (const float*)d_in[2];
    const int*   angles       = (const int*)  d_in[3];
    const float* kern         = (const float*)d_in[4];
    const float* center_k     = (const float*)d_in[5];
    const float* bias         = (const float*)d_in[6];
    float* out = (float*)d_out;

    prep_B<<<(NCHUNKS*128*128 + 255)/256, 256>>>(kern, center_k);

    cudaFuncSetAttribute(geodesic_hmma_kernel,
                         cudaFuncAttributeMaxDynamicSharedMemorySize, SMEM_TOTAL);
    geodesic_hmma_kernel<<<NTILES, THREADS, SMEM_TOTAL>>>(
        y, contributors, weights_bary, angles, bias, out);
}

// round 7
// speedup vs baseline: 1.6942x; 1.1122x over previous
#include <cuda_runtime.h>
#include <cuda_bf16.h>
#include <cstdint>

typedef uint32_t u32; typedef uint64_t u64;

#define NVERT 20000
#define NDIRS 8
#define THREADS 256
#define VTILE 32              // vertices per CTA  -> 64 m-rows
#define NTILES 625            // 20000/32 exact
#define NCHUNKS 9             // 8 rings + 1 center chunk, Kc=128 each

// ---- B chunk images (hi/lo bf16), pre-swizzled, rebuilt each launch ----
__device__ __align__(16) __nv_bfloat16 gBh[NCHUNKS][16384];   // [chunk][128n x 128k]
__device__ __align__(16) __nv_bfloat16 gBl[NCHUNKS][16384];

// element (row,k) byte offset in a row-major tile: row stride 256B,
// 16B chunks XOR-swizzled by (row&7) -> conflict-free LDSM
__device__ __host__ __forceinline__ u32 tile_off(int row, int k) {
    return (u32)(row * 256 + (((k >> 3) ^ (row & 7)) << 4) + (k & 7) * 2);
}

__device__ __forceinline__ u32 smem_u32(const void* p) {
    u32 a; asm("{ .reg .u64 t; cvta.to.shared.u64 t, %1; cvt.u32.u64 %0, t; }" : "=r"(a) : "l"(p));
    return a;
}
__device__ __forceinline__ void ldsm4(u32 r[4], u32 addr) {
    asm volatile("ldmatrix.sync.aligned.m8n8.x4.shared.b16 {%0,%1,%2,%3}, [%4];"
                 : "=r"(r[0]), "=r"(r[1]), "=r"(r[2]), "=r"(r[3]) : "r"(addr));
}
__device__ __forceinline__ void mma16816(float c[4], const u32 a[4], u32 b0, u32 b1) {
    asm volatile(
        "mma.sync.aligned.m16n8k16.row.col.f32.bf16.bf16.f32 "
        "{%0,%1,%2,%3}, {%4,%5,%6,%7}, {%8,%9}, {%0,%1,%2,%3};"
        : "+f"(c[0]), "+f"(c[1]), "+f"(c[2]), "+f"(c[3])
        : "r"(a[0]), "r"(a[1]), "r"(a[2]), "r"(a[3]), "r"(b0), "r"(b1));
}
__device__ __forceinline__ void cp16(u32 dst, const void* src) {
    asm volatile("cp.async.cg.shared.global [%0], [%1], 16;" :: "r"(dst), "l"(src) : "memory");
}
__device__ __forceinline__ void cp_commit_waitall() {
    asm volatile("cp.async.commit_group;\n\tcp.async.wait_group 0;" ::: "memory");
}

// ---- prep kernel: build swizzled bf16 hi/lo B-chunk images ----
// n = f*8 + d ; k = dp*16 + c
__global__ void prep_B(const float* __restrict__ kern, const float* __restrict__ ck) {
    int id = blockIdx.x * blockDim.x + threadIdx.x;     // 147456
    if (id >= NCHUNKS * 128 * 128) return;
    int k  = id & 127;
    int n  = (id >> 7) & 127;
    int kc = id >> 14;
    int f = n >> 3, d = n & 7;
    int dp = k >> 4, c = k & 15;
    float val;
    if (kc < 8) {
        int dw = (dp - d) & 7;
        val = kern[((kc * 8 + dw) * 16 + c) * 16 + f];
    } else {
        val = (dp == d) ? ck[c * 16 + f] : 0.f;
    }
    __nv_bfloat16 hi = __float2bfloat16(val);
    __nv_bfloat16 lo = __float2bfloat16(val - __bfloat162float(hi));
    u32 e = tile_off(n, k) >> 1;
    gBh[kc][e] = hi;
    gBl[kc][e] = lo;
}

// ---- smem layout (byte offsets): A 64x128 hi/lo + B 128x128 hi/lo = 96 KB ----
#define SAH 0
#define SAL 16384
#define SBH 32768
#define SBL 65536
#define SMEM_TOTAL 98304
#define A_LO_OFF 16384
#define B_LO_OFF 32768

// split one 16-float k-segment into hi/lo bf16 and store into both A images
__device__ __forceinline__ void store_row(char* sm, int m, int dp, const float* z) {
    #pragma unroll
    for (int g = 0; g < 2; ++g) {
        u32 H[4], L[4];
        #pragma unroll
        for (int q = 0; q < 4; ++q) {
            float a = z[g*8 + 2*q], b = z[g*8 + 2*q + 1];
            __nv_bfloat16 ha = __float2bfloat16(a);
            __nv_bfloat16 hb = __float2bfloat16(b);
            __nv_bfloat162 hh; hh.x = ha; hh.y = hb;
            __nv_bfloat162 ll;
            ll.x = __float2bfloat16(a - __bfloat162float(ha));
            ll.y = __float2bfloat16(b - __bfloat162float(hb));
            H[q] = *reinterpret_cast<u32*>(&hh);
            L[q] = *reinterpret_cast<u32*>(&ll);
        }
        u32 off = (u32)(m * 256 + (((dp*2 + g) ^ (m & 7)) << 4));
        *reinterpret_cast<uint4*>(sm + SAH + off) = make_uint4(H[0],H[1],H[2],H[3]);
        *reinterpret_cast<uint4*>(sm + SAL + off) = make_uint4(L[0],L[1],L[2],L[3]);
    }
}

__global__ __launch_bounds__(THREADS, 2)
void geodesic_hmma_kernel(const float* __restrict__ y,
                          const int*   __restrict__ contributors,
                          const float* __restrict__ weights_bary,
                          const int*   __restrict__ angles,
                          const float* __restrict__ bias,
                          float*       __restrict__ out)
{
    extern __shared__ char sm[];
    const u32 smb = smem_u32(sm);
    const int tid = threadIdx.x;
    const int wid = tid >> 5;
    const int lid = tid & 31;
    const int v0  = blockIdx.x * VTILE;         // 32 vertices => 64 rows (m = vl*2 + b)
    const int m0  = (wid >> 1) * 16;            // warp's 16-row m-strip (4 strips)
    const int nh  = wid & 1;                    // warp's n-half (64 cols)

    // accumulators: 8 n-tiles x 4 fp32
    float acc[32];
    #pragma unroll
    for (int i = 0; i < 32; ++i) acc[i] = 0.f;

    const int lrow  = (lid & 7) + ((lid >> 3) & 1) * 8;
    const int khalf = (lid >> 4);

    // hoisted ldmatrix addressing: base + (cc4 ^ xorm), lo-image at fixed offset
    const int mA = m0 + lrow;
    const u32 a_base = smb + SAH + (u32)(mA * 256);
    const u32 a_xor  = (u32)((mA & 7) << 4);
    u32 b_base[4], b_xor[4];
    #pragma unroll
    for (int p = 0; p < 4; ++p) {
        int nB = nh*64 + p*16 + lrow;
        b_base[p] = smb + SBH + (u32)(nB * 256);
        b_xor[p]  = (u32)((nB & 7) << 4);
    }

    const float4* y4 = (const float4*)y;

    #pragma unroll 1
    for (int kc = 0; kc < NCHUNKS; ++kc) {
        if (kc > 0) __syncthreads();       // everyone done reading A and B of prev chunk

        // ---- issue async B-chunk copy first (hides under gather) ----
        {
            const char* sh = (const char*)(&gBh[kc][0]);
            const char* sl = (const char*)(&gBl[kc][0]);
            #pragma unroll
            for (int i = 0; i < 8; ++i) {
                u32 off = (u32)(tid + i * THREADS) * 16;
                cp16(smb + SBH + off, sh + off);
                cp16(smb + SBL + off, sl + off);
            }
        }

        // ---- gather: one (v,dp) task per thread ----
        {
            int dp = tid & 7;
            int vl = tid >> 3;                   // 0..31
            int v  = v0 + vl;
            float z0[16], z1[16];
            if (kc < 8) {
                int ibase = ((v * 8 + kc) * 8 + dp) * 3;
                int   i0 = contributors[ibase+0] * 8 + angles[ibase+0];
                int   i1 = contributors[ibase+1] * 8 + angles[ibase+1];
                int   i2 = contributors[ibase+2] * 8 + angles[ibase+2];
                float w0 = weights_bary[ibase+0];
                float w1 = weights_bary[ibase+1];
                float w2 = weights_bary[ibase+2];
                const float4* p00 = y4 + (u32)i0 * 4;
                const float4* p01 = y4 + (u32)i1 * 4;
                const float4* p02 = y4 + (u32)i2 * 4;
                const float4* p10 = p00 + NVERT * NDIRS * 4;
                const float4* p11 = p01 + NVERT * NDIRS * 4;
                const float4* p12 = p02 + NVERT * NDIRS * 4;
                float4 a0[4], a1[4], a2[4], b0[4], b1[4], b2[4];
                #pragma unroll
                for (int q = 0; q < 4; ++q) { a0[q]=__ldg(p00+q); a1[q]=__ldg(p01+q); a2[q]=__ldg(p02+q);
                                              b0[q]=__ldg(p10+q); b1[q]=__ldg(p11+q); b2[q]=__ldg(p12+q); }
                #pragma unroll
                for (int q = 0; q < 4; ++q) {
                    z0[q*4+0] = w0*a0[q].x + w1*a1[q].x + w2*a2[q].x;
                    z0[q*4+1] = w0*a0[q].y + w1*a1[q].y + w2*a2[q].y;
                    z0[q*4+2] = w0*a0[q].z + w1*a1[q].z + w2*a2[q].z;
                    z0[q*4+3] = w0*a0[q].w + w1*a1[q].w + w2*a2[q].w;
                    z1[q*4+0] = w0*b0[q].x + w1*b1[q].x + w2*b2[q].x;
                    z1[q*4+1] = w0*b0[q].y + w1*b1[q].y + w2*b2[q].y;
                    z1[q*4+2] = w0*b0[q].z + w1*b1[q].z + w2*b2[q].z;
                    z1[q*4+3] = w0*b0[q].w + w1*b1[q].w + w2*b2[q].w;
                }
            } else {
                int idx = v * 8 + dp;
                const float4* p0 = y4 + (u32)idx * 4;
                const float4* p1 = p0 + NVERT * NDIRS * 4;
                #pragma unroll
                for (int q = 0; q < 4; ++q) {
                    float4 a = __ldg(p0+q), b = __ldg(p1+q);
                    z0[q*4+0]=a.x; z0[q*4+1]=a.y; z0[q*4+2]=a.z; z0[q*4+3]=a.w;
                    z1[q*4+0]=b.x; z1[q*4+1]=b.y; z1[q*4+2]=b.z; z1[q*4+3]=b.w;
                }
            }
            store_row(sm, vl*2 + 0, dp, z0);
            store_row(sm, vl*2 + 1, dp, z1);
        }

        cp_commit_waitall();
        __syncthreads();

        // ---- HMMA: 8 ksteps; frags loaded ONCE, 3 split-MMAs from registers ----
        #pragma unroll 1
        for (int ks = 0; ks < 8; ++ks) {
            u32 cc4 = (u32)((ks*2 + khalf) << 4);
            u32 aaddr = a_base + (cc4 ^ a_xor);
            u32 afh[4], afl[4];
            ldsm4(afh, aaddr);
            ldsm4(afl, aaddr + A_LO_OFF);
            #pragma unroll
            for (int p = 0; p < 4; ++p) {
                u32 baddr = b_base[p] + (cc4 ^ b_xor[p]);
                u32 bfh[4], bfl[4];
                ldsm4(bfh, baddr);
                ldsm4(bfl, baddr + B_LO_OFF);
                mma16816(&acc[(p*2+0)*4], afh, bfh[0], bfh[2]);   // hi*hi
                mma16816(&acc[(p*2+1)*4], afh, bfh[1], bfh[3]);
                mma16816(&acc[(p*2+0)*4], afh, bfl[0], bfl[2]);   // hi*lo
                mma16816(&acc[(p*2+1)*4], afh, bfl[1], bfl[3]);
                mma16816(&acc[(p*2+0)*4], afl, bfh[0], bfh[2]);   // lo*hi
                mma16816(&acc[(p*2+1)*4], afl, bfh[1], bfh[3]);
            }
        }
    }

    // ---- epilogue: bias + relu + max over d ----
    // f = nh*8 + t ; d = (lid&3)*2 + {0,1}
    #pragma unroll
    for (int t = 0; t < 8; ++t) {
        int f = nh*8 + t;
        float mlo = fmaxf(acc[t*4+0], acc[t*4+1]);
        float mhi = fmaxf(acc[t*4+2], acc[t*4+3]);
        mlo = fmaxf(mlo, __shfl_xor_sync(0xffffffffu, mlo, 1));
        mlo = fmaxf(mlo, __shfl_xor_sync(0xffffffffu, mlo, 2));
        mhi = fmaxf(mhi, __shfl_xor_sync(0xffffffffu, mhi, 1));
        mhi = fmaxf(mhi, __shfl_xor_sync(0xffffffffu, mhi, 2));
        if ((lid & 3) == (t & 3)) {
            float bf_ = __ldg(&bias[f]);
            int r = m0 + (lid >> 2);
            int b = r & 1, v = v0 + (r >> 1);
            out[((u32)b * NVERT + v) * 16 + f] = fmaxf(mlo + bf_, 0.f);
            r += 8; b = r & 1; v = v0 + (r >> 1);
            out[((u32)b * NVERT + v) * 16 + f] = fmaxf(mhi + bf_, 0.f);
        }
    }
}

extern "C" void kernel_launch(void* const* d_in, const int* in_sizes, int n_in,
                              void* d_out, int out_size)
{
    (void)in_sizes; (void)n_in; (void)out_size;
    const float* y            = (const float*)d_in[0];
    const int*   contributors = (const int*)  d_in[1];
    const float* weights_bary = (const float*)d_in[2];
    const int*   angles       = (const int*)  d_in[3];
    const float* kern         = (const float*)d_in[4];
    const float* center_k     = (const float*)d_in[5];
    const float* bias         = (const float*)d_in[6];
    float* out = (float*)d_out;

    prep_B<<<(NCHUNKS*128*128 + 255)/256, 256>>>(kern, center_k);

    cudaFuncSetAttribute(geodesic_hmma_kernel,
                         cudaFuncAttributeMaxDynamicSharedMemorySize, SMEM_TOTAL);
    geodesic_hmma_kernel<<<NTILES, THREADS, SMEM_TOTAL>>>(
        y, contributors, weights_bary, angles, bias, out);
}

// round 8
// speedup vs baseline: 1.6961x; 1.0011x over previous
#include <cuda_runtime.h>
#include <cuda_bf16.h>
#include <cstdint>

typedef uint32_t u32; typedef uint64_t u64;

#define NVERT 20000
#define NDIRS 8
#define THREADS 256
#define VTILE 32              // vertices per CTA  -> 64 m-rows
#define NTILES 625            // 20000/32 exact
#define NCHUNKS 9             // 8 rings + 1 center chunk, Kc=128 each

// ---- B chunk images (hi/lo bf16), pre-swizzled, rebuilt each launch ----
__device__ __align__(16) __nv_bfloat16 gBh[NCHUNKS][16384];   // [chunk][128n x 128k]
__device__ __align__(16) __nv_bfloat16 gBl[NCHUNKS][16384];

// element (row,k) byte offset in a row-major tile: row stride 256B,
// 16B chunks XOR-swizzled by (row&7) -> conflict-free LDSM
__device__ __host__ __forceinline__ u32 tile_off(int row, int k) {
    return (u32)(row * 256 + (((k >> 3) ^ (row & 7)) << 4) + (k & 7) * 2);
}

__device__ __forceinline__ u32 smem_u32(const void* p) {
    u32 a; asm("{ .reg .u64 t; cvta.to.shared.u64 t, %1; cvt.u32.u64 %0, t; }" : "=r"(a) : "l"(p));
    return a;
}
__device__ __forceinline__ void ldsm4(u32 r[4], u32 addr) {
    asm volatile("ldmatrix.sync.aligned.m8n8.x4.shared.b16 {%0,%1,%2,%3}, [%4];"
                 : "=r"(r[0]), "=r"(r[1]), "=r"(r[2]), "=r"(r[3]) : "r"(addr));
}
__device__ __forceinline__ void mma16816(float c[4], const u32 a[4], u32 b0, u32 b1) {
    asm volatile(
        "mma.sync.aligned.m16n8k16.row.col.f32.bf16.bf16.f32 "
        "{%0,%1,%2,%3}, {%4,%5,%6,%7}, {%8,%9}, {%0,%1,%2,%3};"
        : "+f"(c[0]), "+f"(c[1]), "+f"(c[2]), "+f"(c[3])
        : "r"(a[0]), "r"(a[1]), "r"(a[2]), "r"(a[3]), "r"(b0), "r"(b1));
}
__device__ __forceinline__ void cp16(u32 dst, const void* src) {
    asm volatile("cp.async.cg.shared.global [%0], [%1], 16;" :: "r"(dst), "l"(src) : "memory");
}
__device__ __forceinline__ void cp_commit_waitall() {
    asm volatile("cp.async.commit_group;\n\tcp.async.wait_group 0;" ::: "memory");
}

// ---- prep kernel: build swizzled bf16 hi/lo B-chunk images ----
// n = f*8 + d ; k = dp*16 + c
__global__ void prep_B(const float* __restrict__ kern, const float* __restrict__ ck) {
    int id = blockIdx.x * blockDim.x + threadIdx.x;     // 147456
    if (id >= NCHUNKS * 128 * 128) return;
    int k  = id & 127;
    int n  = (id >> 7) & 127;
    int kc = id >> 14;
    int f = n >> 3, d = n & 7;
    int dp = k >> 4, c = k & 15;
    float val;
    if (kc < 8) {
        int dw = (dp - d) & 7;
        val = kern[((kc * 8 + dw) * 16 + c) * 16 + f];
    } else {
        val = (dp == d) ? ck[c * 16 + f] : 0.f;
    }
    __nv_bfloat16 hi = __float2bfloat16(val);
    __nv_bfloat16 lo = __float2bfloat16(val - __bfloat162float(hi));
    u32 e = tile_off(n, k) >> 1;
    gBh[kc][e] = hi;
    gBl[kc][e] = lo;
}

// ---- smem layout (byte offsets): A 64x128 hi/lo + B 128x128 hi/lo = 96 KB ----
#define SAH 0
#define SAL 16384
#define SBH 32768
#define SBL 65536
#define SMEM_TOTAL 98304
#define A_LO_OFF 16384
#define B_LO_OFF 32768

// split one 16-float k-segment into hi/lo bf16 and store into both A images
__device__ __forceinline__ void store_row(char* sm, int m, int dp, const float* z) {
    #pragma unroll
    for (int g = 0; g < 2; ++g) {
        u32 H[4], L[4];
        #pragma unroll
        for (int q = 0; q < 4; ++q) {
            float a = z[g*8 + 2*q], b = z[g*8 + 2*q + 1];
            __nv_bfloat16 ha = __float2bfloat16(a);
            __nv_bfloat16 hb = __float2bfloat16(b);
            __nv_bfloat162 hh; hh.x = ha; hh.y = hb;
            __nv_bfloat162 ll;
            ll.x = __float2bfloat16(a - __bfloat162float(ha));
            ll.y = __float2bfloat16(b - __bfloat162float(hb));
            H[q] = *reinterpret_cast<u32*>(&hh);
            L[q] = *reinterpret_cast<u32*>(&ll);
        }
        u32 off = (u32)(m * 256 + (((dp*2 + g) ^ (m & 7)) << 4));
        *reinterpret_cast<uint4*>(sm + SAH + off) = make_uint4(H[0],H[1],H[2],H[3]);
        *reinterpret_cast<uint4*>(sm + SAL + off) = make_uint4(L[0],L[1],L[2],L[3]);
    }
}

__global__ __launch_bounds__(THREADS, 2)
void geodesic_hmma_kernel(const float* __restrict__ y,
                          const int*   __restrict__ contributors,
                          const float* __restrict__ weights_bary,
                          const int*   __restrict__ angles,
                          const float* __restrict__ bias,
                          float*       __restrict__ out)
{
    extern __shared__ char sm[];
    const u32 smb = smem_u32(sm);
    const int tid = threadIdx.x;
    const int wid = tid >> 5;
    const int lid = tid & 31;
    const int v0  = blockIdx.x * VTILE;         // 32 vertices => 64 rows (m = vl*2 + b)
    const int m0  = (wid >> 1) * 16;            // warp's 16-row m-strip (4 strips)
    const int nh  = wid & 1;                    // warp's n-half (64 cols)

    // accumulators: 8 n-tiles x 4 fp32
    float acc[32];
    #pragma unroll
    for (int i = 0; i < 32; ++i) acc[i] = 0.f;

    const int lrow  = (lid & 7) + ((lid >> 3) & 1) * 8;
    const int khalf = (lid >> 4);

    // hoisted ldmatrix addressing: base + (cc4 ^ xorm), lo-image at fixed offset
    const int mA = m0 + lrow;
    const u32 a_base = smb + SAH + (u32)(mA * 256);
    const u32 a_xor  = (u32)((mA & 7) << 4);
    u32 b_base[4], b_xor[4];
    #pragma unroll
    for (int p = 0; p < 4; ++p) {
        int nB = nh*64 + p*16 + lrow;
        b_base[p] = smb + SBH + (u32)(nB * 256);
        b_xor[p]  = (u32)((nB & 7) << 4);
    }

    const float4* y4 = (const float4*)y;

    #pragma unroll 1
    for (int kc = 0; kc < NCHUNKS; ++kc) {
        if (kc > 0) __syncthreads();       // everyone done reading A and B of prev chunk

        // ---- issue async B-chunk copy first (hides under gather) ----
        {
            const char* sh = (const char*)(&gBh[kc][0]);
            const char* sl = (const char*)(&gBl[kc][0]);
            #pragma unroll
            for (int i = 0; i < 8; ++i) {
                u32 off = (u32)(tid + i * THREADS) * 16;
                cp16(smb + SBH + off, sh + off);
                cp16(smb + SBL + off, sl + off);
            }
        }

        // ---- gather: one (v,dp) task per thread ----
        {
            int dp = tid & 7;
            int vl = tid >> 3;                   // 0..31
            int v  = v0 + vl;
            float z0[16], z1[16];
            if (kc < 8) {
                int ibase = ((v * 8 + kc) * 8 + dp) * 3;
                int   i0 = contributors[ibase+0] * 8 + angles[ibase+0];
                int   i1 = contributors[ibase+1] * 8 + angles[ibase+1];
                int   i2 = contributors[ibase+2] * 8 + angles[ibase+2];
                float w0 = weights_bary[ibase+0];
                float w1 = weights_bary[ibase+1];
                float w2 = weights_bary[ibase+2];
                const float4* p00 = y4 + (u32)i0 * 4;
                const float4* p01 = y4 + (u32)i1 * 4;
                const float4* p02 = y4 + (u32)i2 * 4;
                const float4* p10 = p00 + NVERT * NDIRS * 4;
                const float4* p11 = p01 + NVERT * NDIRS * 4;
                const float4* p12 = p02 + NVERT * NDIRS * 4;
                float4 a0[4], a1[4], a2[4], b0[4], b1[4], b2[4];
                #pragma unroll
                for (int q = 0; q < 4; ++q) { a0[q]=__ldg(p00+q); a1[q]=__ldg(p01+q); a2[q]=__ldg(p02+q);
                                              b0[q]=__ldg(p10+q); b1[q]=__ldg(p11+q); b2[q]=__ldg(p12+q); }
                #pragma unroll
                for (int q = 0; q < 4; ++q) {
                    z0[q*4+0] = w0*a0[q].x + w1*a1[q].x + w2*a2[q].x;
                    z0[q*4+1] = w0*a0[q].y + w1*a1[q].y + w2*a2[q].y;
                    z0[q*4+2] = w0*a0[q].z + w1*a1[q].z + w2*a2[q].z;
                    z0[q*4+3] = w0*a0[q].w + w1*a1[q].w + w2*a2[q].w;
                    z1[q*4+0] = w0*b0[q].x + w1*b1[q].x + w2*b2[q].x;
                    z1[q*4+1] = w0*b0[q].y + w1*b1[q].y + w2*b2[q].y;
                    z1[q*4+2] = w0*b0[q].z + w1*b1[q].z + w2*b2[q].z;
                    z1[q*4+3] = w0*b0[q].w + w1*b1[q].w + w2*b2[q].w;
                }
            } else {
                int idx = v * 8 + dp;
                const float4* p0 = y4 + (u32)idx * 4;
                const float4* p1 = p0 + NVERT * NDIRS * 4;
                #pragma unroll
                for (int q = 0; q < 4; ++q) {
                    float4 a = __ldg(p0+q), b = __ldg(p1+q);
                    z0[q*4+0]=a.x; z0[q*4+1]=a.y; z0[q*4+2]=a.z; z0[q*4+3]=a.w;
                    z1[q*4+0]=b.x; z1[q*4+1]=b.y; z1[q*4+2]=b.z; z1[q*4+3]=b.w;
                }
            }
            store_row(sm, vl*2 + 0, dp, z0);
            store_row(sm, vl*2 + 1, dp, z1);
        }

        cp_commit_waitall();
        __syncthreads();

        // ---- HMMA: batch-load all frags, then 24 MMAs at same-acc distance 8 ----
        #pragma unroll 1
        for (int ks = 0; ks < 8; ++ks) {
            u32 cc4 = (u32)((ks*2 + khalf) << 4);
            u32 aaddr = a_base + (cc4 ^ a_xor);
            u32 afh[4], afl[4];
            ldsm4(afh, aaddr);
            ldsm4(afl, aaddr + A_LO_OFF);
            u32 bfh[4][4], bfl[4][4];
            #pragma unroll
            for (int p = 0; p < 4; ++p) {
                u32 baddr = b_base[p] + (cc4 ^ b_xor[p]);
                ldsm4(bfh[p], baddr);
                ldsm4(bfl[p], baddr + B_LO_OFF);
            }
            // hi*hi: evens then odds
            #pragma unroll
            for (int p = 0; p < 4; ++p) mma16816(&acc[(p*2+0)*4], afh, bfh[p][0], bfh[p][2]);
            #pragma unroll
            for (int p = 0; p < 4; ++p) mma16816(&acc[(p*2+1)*4], afh, bfh[p][1], bfh[p][3]);
            // hi*lo
            #pragma unroll
            for (int p = 0; p < 4; ++p) mma16816(&acc[(p*2+0)*4], afh, bfl[p][0], bfl[p][2]);
            #pragma unroll
            for (int p = 0; p < 4; ++p) mma16816(&acc[(p*2+1)*4], afh, bfl[p][1], bfl[p][3]);
            // lo*hi
            #pragma unroll
            for (int p = 0; p < 4; ++p) mma16816(&acc[(p*2+0)*4], afl, bfh[p][0], bfh[p][2]);
            #pragma unroll
            for (int p = 0; p < 4; ++p) mma16816(&acc[(p*2+1)*4], afl, bfh[p][1], bfh[p][3]);
        }
    }

    // ---- epilogue: bias + relu + max over d ----
    // f = nh*8 + t ; d = (lid&3)*2 + {0,1}
    #pragma unroll
    for (int t = 0; t < 8; ++t) {
        int f = nh*8 + t;
        float mlo = fmaxf(acc[t*4+0], acc[t*4+1]);
        float mhi = fmaxf(acc[t*4+2], acc[t*4+3]);
        mlo = fmaxf(mlo, __shfl_xor_sync(0xffffffffu, mlo, 1));
        mlo = fmaxf(mlo, __shfl_xor_sync(0xffffffffu, mlo, 2));
        mhi = fmaxf(mhi, __shfl_xor_sync(0xffffffffu, mhi, 1));
        mhi = fmaxf(mhi, __shfl_xor_sync(0xffffffffu, mhi, 2));
        if ((lid & 3) == (t & 3)) {
            float bf_ = __ldg(&bias[f]);
            int r = m0 + (lid >> 2);
            int b = r & 1, v = v0 + (r >> 1);
            out[((u32)b * NVERT + v) * 16 + f] = fmaxf(mlo + bf_, 0.f);
            r += 8; b = r & 1; v = v0 + (r >> 1);
            out[((u32)b * NVERT + v) * 16 + f] = fmaxf(mhi + bf_, 0.f);
        }
    }
}

extern "C" void kernel_launch(void* const* d_in, const int* in_sizes, int n_in,
                              void* d_out, int out_size)
{
    (void)in_sizes; (void)n_in; (void)out_size;
    const float* y            = (const float*)d_in[0];
    const int*   contributors = (const int*)  d_in[1];
    const float* weights_bary = (const float*)d_in[2];
    const int*   angles       = (const int*)  d_in[3];
    const float* kern         = (const float*)d_in[4];
    const float* center_k     = (const float*)d_in[5];
    const float* bias         = (const float*)d_in[6];
    float* out = (float*)d_out;

    prep_B<<<(NCHUNKS*128*128 + 255)/256, 256>>>(kern, center_k);

    cudaFuncSetAttribute(geodesic_hmma_kernel,
                         cudaFuncAttributeMaxDynamicSharedMemorySize, SMEM_TOTAL);
    geodesic_hmma_kernel<<<NTILES, THREADS, SMEM_TOTAL>>>(
        y, contributors, weights_bary, angles, bias, out);
}

// round 9
// speedup vs baseline: 2.4935x; 1.4701x over previous
#include <cuda_runtime.h>
#include <cuda_bf16.h>
#include <cstdint>

typedef uint32_t u32; typedef uint64_t u64;

#define NVERT 20000
#define NDIRS 8
#define THREADS 256
#define VTILE 32              // vertices per CTA  -> 64 m-rows
#define NTILES 625            // 20000/32 exact
#define NCHUNKS 9             // 8 rings + 1 center chunk, Kc=128 each

// ---- B chunk images (hi/lo bf16), pre-swizzled, rebuilt each launch ----
__device__ __align__(16) __nv_bfloat16 gBh[NCHUNKS][16384];   // [chunk][128n x 128k]
__device__ __align__(16) __nv_bfloat16 gBl[NCHUNKS][16384];

// element (row,k) byte offset in a row-major tile: row stride 256B,
// 16B chunks XOR-swizzled by (row&7) -> conflict-free LDSM
__device__ __host__ __forceinline__ u32 tile_off(int row, int k) {
    return (u32)(row * 256 + (((k >> 3) ^ (row & 7)) << 4) + (k & 7) * 2);
}

__device__ __forceinline__ u32 smem_u32(const void* p) {
    u32 a; asm("{ .reg .u64 t; cvta.to.shared.u64 t, %1; cvt.u32.u64 %0, t; }" : "=r"(a) : "l"(p));
    return a;
}
__device__ __forceinline__ void ldsm4(u32 r[4], u32 addr) {
    asm volatile("ldmatrix.sync.aligned.m8n8.x4.shared.b16 {%0,%1,%2,%3}, [%4];"
                 : "=r"(r[0]), "=r"(r[1]), "=r"(r[2]), "=r"(r[3]) : "r"(addr));
}
__device__ __forceinline__ void mma16816(float c[4], const u32 a[4], u32 b0, u32 b1) {
    asm volatile(
        "mma.sync.aligned.m16n8k16.row.col.f32.bf16.bf16.f32 "
        "{%0,%1,%2,%3}, {%4,%5,%6,%7}, {%8,%9}, {%0,%1,%2,%3};"
        : "+f"(c[0]), "+f"(c[1]), "+f"(c[2]), "+f"(c[3])
        : "r"(a[0]), "r"(a[1]), "r"(a[2]), "r"(a[3]), "r"(b0), "r"(b1));
}
__device__ __forceinline__ void cp16(u32 dst, const void* src) {
    asm volatile("cp.async.cg.shared.global [%0], [%1], 16;" :: "r"(dst), "l"(src) : "memory");
}
__device__ __forceinline__ void cp_commit_waitall() {
    asm volatile("cp.async.commit_group;\n\tcp.async.wait_group 0;" ::: "memory");
}

// ---- prep kernel: build swizzled bf16 hi/lo B-chunk images ----
// n = f*8 + d ; k = dp*16 + c
__global__ void prep_B(const float* __restrict__ kern, const float* __restrict__ ck) {
    int id = blockIdx.x * blockDim.x + threadIdx.x;     // 147456
    if (id >= NCHUNKS * 128 * 128) return;
    int k  = id & 127;
    int n  = (id >> 7) & 127;
    int kc = id >> 14;
    int f = n >> 3, d = n & 7;
    int dp = k >> 4, c = k & 15;
    float val;
    if (kc < 8) {
        int dw = (dp - d) & 7;
        val = kern[((kc * 8 + dw) * 16 + c) * 16 + f];
    } else {
        val = (dp == d) ? ck[c * 16 + f] : 0.f;
    }
    __nv_bfloat16 hi = __float2bfloat16(val);
    __nv_bfloat16 lo = __float2bfloat16(val - __bfloat162float(hi));
    u32 e = tile_off(n, k) >> 1;
    gBh[kc][e] = hi;
    gBl[kc][e] = lo;
}

// ---- smem layout (byte offsets): A 64x128 hi/lo + B 128x128 hi/lo = 96 KB ----
#define SAH 0
#define SAL 16384
#define SBH 32768
#define SBL 65536
#define SMEM_TOTAL 98304
#define A_LO_OFF 16384
#define B_LO_OFF 32768

// convert 4 floats (k-quad q of row m) to hi/lo bf16 and store 8B each image
__device__ __forceinline__ void store_quad(char* sm, int m, int dp, int q, float4 z) {
    __nv_bfloat162 h0 = __floats2bfloat162_rn(z.x, z.y);
    __nv_bfloat162 h1 = __floats2bfloat162_rn(z.z, z.w);
    __nv_bfloat162 l0 = __floats2bfloat162_rn(z.x - __low2float(h0), z.y - __high2float(h0));
    __nv_bfloat162 l1 = __floats2bfloat162_rn(z.z - __low2float(h1), z.w - __high2float(h1));
    u32 off = (u32)(m * 256 + ((((dp << 1) | (q >> 1)) ^ (m & 7)) << 4) + (q & 1) * 8);
    uint2 H; H.x = *reinterpret_cast<u32*>(&h0); H.y = *reinterpret_cast<u32*>(&h1);
    uint2 L; L.x = *reinterpret_cast<u32*>(&l0); L.y = *reinterpret_cast<u32*>(&l1);
    *reinterpret_cast<uint2*>(sm + SAH + off) = H;
    *reinterpret_cast<uint2*>(sm + SAL + off) = L;
}

__global__ __launch_bounds__(THREADS, 2)
void geodesic_hmma_kernel(const float* __restrict__ y,
                          const int*   __restrict__ contributors,
                          const float* __restrict__ weights_bary,
                          const int*   __restrict__ angles,
                          const float* __restrict__ bias,
                          float*       __restrict__ out)
{
    extern __shared__ char sm[];
    const u32 smb = smem_u32(sm);
    const int tid = threadIdx.x;
    const int wid = tid >> 5;
    const int lid = tid & 31;
    const int v0  = blockIdx.x * VTILE;         // 32 vertices => 64 rows (m = vl*2 + b)
    const int m0  = (wid >> 1) * 16;            // warp's 16-row m-strip (4 strips)
    const int nh  = wid & 1;                    // warp's n-half (64 cols)

    // accumulators: 8 n-tiles x 4 fp32
    float acc[32];
    #pragma unroll
    for (int i = 0; i < 32; ++i) acc[i] = 0.f;

    const int lrow  = (lid & 7) + ((lid >> 3) & 1) * 8;
    const int khalf = (lid >> 4);

    // hoisted ldmatrix addressing: base + (cc4 ^ xorm), lo-image at fixed offset
    const int mA = m0 + lrow;
    const u32 a_base = smb + SAH + (u32)(mA * 256);
    const u32 a_xor  = (u32)((mA & 7) << 4);
    u32 b_base[4], b_xor[4];
    #pragma unroll
    for (int p = 0; p < 4; ++p) {
        int nB = nh*64 + p*16 + lrow;
        b_base[p] = smb + SBH + (u32)(nB * 256);
        b_xor[p]  = (u32)((nB & 7) << 4);
    }

    // quad-cooperative gather geometry
    const int q     = lid & 3;                  // c-quad (16B) within row
    const int qt    = tid >> 2;                 // quad id 0..63
    const int lbase = lid & ~3;                 // quad's first lane in warp

    const float4* y4 = (const float4*)y;

    #pragma unroll 1
    for (int kc = 0; kc < NCHUNKS; ++kc) {
        if (kc > 0) __syncthreads();       // everyone done reading A and B of prev chunk

        // ---- issue async B-chunk copy first (hides under gather) ----
        {
            const char* sh = (const char*)(&gBh[kc][0]);
            const char* sl = (const char*)(&gBl[kc][0]);
            #pragma unroll
            for (int i = 0; i < 8; ++i) {
                u32 off = (u32)(tid + i * THREADS) * 16;
                cp16(smb + SBH + off, sh + off);
                cp16(smb + SBL + off, sl + off);
            }
        }

        // ---- gather: one (v,dp) task per QUAD; lane q owns 16B c-quad ----
        #pragma unroll 1
        for (int rr = 0; rr < 4; ++rr) {
            int t  = qt + rr * 64;               // 0..255
            int dp = t & 7;
            int vl = t >> 3;                     // 0..31
            int v  = v0 + vl;
            float4 z0, z1;
            if (kc < 8) {
                int ibase = ((v * 8 + kc) * 8 + dp) * 3;
                int   idxv = 0;
                float wv   = 0.f;
                if (q < 3) {
                    idxv = contributors[ibase + q] * 8 + angles[ibase + q];
                    wv   = weights_bary[ibase + q];
                }
                int   i0 = __shfl_sync(0xffffffffu, idxv, lbase + 0);
                int   i1 = __shfl_sync(0xffffffffu, idxv, lbase + 1);
                int   i2 = __shfl_sync(0xffffffffu, idxv, lbase + 2);
                float w0 = __shfl_sync(0xffffffffu, wv,   lbase + 0);
                float w1 = __shfl_sync(0xffffffffu, wv,   lbase + 1);
                float w2 = __shfl_sync(0xffffffffu, wv,   lbase + 2);
                float4 a0 = __ldg(y4 + (u32)i0 * 4 + q);
                float4 a1 = __ldg(y4 + (u32)i1 * 4 + q);
                float4 a2 = __ldg(y4 + (u32)i2 * 4 + q);
                float4 c0 = __ldg(y4 + (u32)i0 * 4 + q + NVERT * NDIRS * 4);
                float4 c1 = __ldg(y4 + (u32)i1 * 4 + q + NVERT * NDIRS * 4);
                float4 c2 = __ldg(y4 + (u32)i2 * 4 + q + NVERT * NDIRS * 4);
                z0.x = w0*a0.x + w1*a1.x + w2*a2.x;
                z0.y = w0*a0.y + w1*a1.y + w2*a2.y;
                z0.z = w0*a0.z + w1*a1.z + w2*a2.z;
                z0.w = w0*a0.w + w1*a1.w + w2*a2.w;
                z1.x = w0*c0.x + w1*c1.x + w2*c2.x;
                z1.y = w0*c0.y + w1*c1.y + w2*c2.y;
                z1.z = w0*c0.z + w1*c1.z + w2*c2.z;
                z1.w = w0*c0.w + w1*c1.w + w2*c2.w;
            } else {
                int idx = v * 8 + dp;
                z0 = __ldg(y4 + (u32)idx * 4 + q);
                z1 = __ldg(y4 + (u32)idx * 4 + q + NVERT * NDIRS * 4);
            }
            store_quad(sm, vl*2 + 0, dp, q, z0);
            store_quad(sm, vl*2 + 1, dp, q, z1);
        }

        cp_commit_waitall();
        __syncthreads();

        // ---- HMMA: batch-load frags, 24 MMAs at same-acc distance 8 ----
        #pragma unroll 1
        for (int ks = 0; ks < 8; ++ks) {
            u32 cc4 = (u32)((ks*2 + khalf) << 4);
            u32 aaddr = a_base + (cc4 ^ a_xor);
            u32 afh[4], afl[4];
            ldsm4(afh, aaddr);
            ldsm4(afl, aaddr + A_LO_OFF);
            u32 bfh[4][4], bfl[4][4];
            #pragma unroll
            for (int p = 0; p < 4; ++p) {
                u32 baddr = b_base[p] + (cc4 ^ b_xor[p]);
                ldsm4(bfh[p], baddr);
                ldsm4(bfl[p], baddr + B_LO_OFF);
            }
            #pragma unroll
            for (int p = 0; p < 4; ++p) mma16816(&acc[(p*2+0)*4], afh, bfh[p][0], bfh[p][2]);
            #pragma unroll
            for (int p = 0; p < 4; ++p) mma16816(&acc[(p*2+1)*4], afh, bfh[p][1], bfh[p][3]);
            #pragma unroll
            for (int p = 0; p < 4; ++p) mma16816(&acc[(p*2+0)*4], afh, bfl[p][0], bfl[p][2]);
            #pragma unroll
            for (int p = 0; p < 4; ++p) mma16816(&acc[(p*2+1)*4], afh, bfl[p][1], bfl[p][3]);
            #pragma unroll
            for (int p = 0; p < 4; ++p) mma16816(&acc[(p*2+0)*4], afl, bfh[p][0], bfh[p][2]);
            #pragma unroll
            for (int p = 0; p < 4; ++p) mma16816(&acc[(p*2+1)*4], afl, bfh[p][1], bfh[p][3]);
        }
    }

    // ---- epilogue: bias + relu + max over d ----
    // f = nh*8 + t ; d = (lid&3)*2 + {0,1}
    #pragma unroll
    for (int t = 0; t < 8; ++t) {
        int f = nh*8 + t;
        float mlo = fmaxf(acc[t*4+0], acc[t*4+1]);
        float mhi = fmaxf(acc[t*4+2], acc[t*4+3]);
        mlo = fmaxf(mlo, __shfl_xor_sync(0xffffffffu, mlo, 1));
        mlo = fmaxf(mlo, __shfl_xor_sync(0xffffffffu, mlo, 2));
        mhi = fmaxf(mhi, __shfl_xor_sync(0xffffffffu, mhi, 1));
        mhi = fmaxf(mhi, __shfl_xor_sync(0xffffffffu, mhi, 2));
        if ((lid & 3) == (t & 3)) {
            float bf_ = __ldg(&bias[f]);
            int r = m0 + (lid >> 2);
            int b = r & 1, v = v0 + (r >> 1);
            out[((u32)b * NVERT + v) * 16 + f] = fmaxf(mlo + bf_, 0.f);
            r += 8; b = r & 1; v = v0 + (r >> 1);
            out[((u32)b * NVERT + v) * 16 + f] = fmaxf(mhi + bf_, 0.f);
        }
    }
}

extern "C" void kernel_launch(void* const* d_in, const int* in_sizes, int n_in,
                              void* d_out, int out_size)
{
    (void)in_sizes; (void)n_in; (void)out_size;
    const float* y            = (const float*)d_in[0];
    const int*   contributors = (const int*)  d_in[1];
    const float* weights_bary = (const float*)d_in[2];
    const int*   angles       = (const int*)  d_in[3];
    const float* kern         = (const float*)d_in[4];
    const float* center_k     = (const float*)d_in[5];
    const float* bias         = (const float*)d_in[6];
    float* out = (float*)d_out;

    prep_B<<<(NCHUNKS*128*128 + 255)/256, 256>>>(kern, center_k);

    cudaFuncSetAttribute(geodesic_hmma_kernel,
                         cudaFuncAttributeMaxDynamicSharedMemorySize, SMEM_TOTAL);
    geodesic_hmma_kernel<<<NTILES, THREADS, SMEM_TOTAL>>>(
        y, contributors, weights_bary, angles, bias, out);
}